// round 11
// baseline (speedup 1.0000x reference)
#include <cuda_runtime.h>

#define S_LEN   3072
#define EDIM    16
#define NHEAD   5
#define NBATCH  32
#define NCHAIN  (NBATCH * NHEAD)   // 160
#define SPLIT   16
#define SEG_LEN (S_LEN / SPLIT)    // 192
#define CHUNKS  8
#define CLEN    (SEG_LEN / CHUNKS) // 24
#define NQUAD   (NBATCH / 4)       // 8

// q->k and q->v offsets in float2 units (folded into LDG immediates)
#define KOFF2 (NHEAD * S_LEN * 8)
#define VOFF2 (2 * NHEAD * S_LEN * 8)

// scratch for params of heads 0..2 (inner): [N][3][S_LEN][E]
__device__ float g_params[(long)NBATCH * 3 * S_LEN * EDIM];
// chunk sums -> exclusive prefixes (in-place): [chain*SPLIT+seg][chunk][i][c]
__device__ float g_prefS[(long)NCHAIN * SPLIT * CHUNKS * 256];
__device__ float g_prefZ[(long)NCHAIN * SPLIT * CHUNKS * 16];
// INCLUSIVE per-segment totals (scan_c sums preceding segments itself)
__device__ float g_totS [(long)NCHAIN * SPLIT * 256];
__device__ float g_totZ [(long)NCHAIN * SPLIT * 16];

__device__ __forceinline__ float softplus_f(float x) {
    // all args here are small (|x| < ~5): unclamped fast form is exact enough
    return __logf(1.0f + __expf(x));
}

// ---------------------------------------------------------------------------
// K1: batch-quad chunk sums + in-segment exclusive prefix.
// grid = NQUAD*SPLIT*NHEAD = 640, block = 256 = 8 chunks x (4 batches x 8).
// One warp = 1 chunk x 4 batches: all 32 lanes read the SAME 64B weight
// region per array -> 1 L1 wavefront per weight LDG serving 4 batches.
// ---------------------------------------------------------------------------
__global__ __launch_bounds__(256, 3) void scan_a(
    const float* __restrict__ x,
    const float* __restrict__ ew,
    const float* __restrict__ eb)
{
    __shared__ __align__(16) float kst[2][CHUNKS][4][16];
    __shared__ float sZ[CHUNKS][4][16];

    const int b    = blockIdx.x;
    const int quad = b / (NHEAD * SPLIT);
    const int rem  = b % (NHEAD * SPLIT);
    const int seg  = rem / NHEAD;
    const int head = rem % NHEAD;
    const int tid  = threadIdx.x;
    const int g    = tid >> 5;          // chunk 0..7
    const int sub  = (tid >> 3) & 3;    // batch within quad
    const int hl   = tid & 7;

    const int n     = quad * 4 + sub;
    const int chain = n * NHEAD + head;
    const float* xw = x + (long)n * S_LEN;
    const int pos0  = seg * SEG_LEN + g * CLEN;

    const long qbase = (long)head * S_LEN * 8 + (long)pos0 * 8 + hl;
    const float2* wq = (const float2*)ew + qbase;
    const float2* bq = (const float2*)eb + qbase;

    float S0[16], S1[16];
#pragma unroll
    for (int i = 0; i < 16; i++) { S0[i] = 0.f; S1[i] = 0.f; }
    float z0 = 0.f, z1 = 0.f;

    for (int s = 0; s < CLEN; s++) {
        const float xv = __ldg(xw + pos0 + s);
        const float2 a  = __ldg(wq + KOFF2 + s * 8);
        const float2 bb = __ldg(bq + KOFF2 + s * 8);
        const float kx = softplus_f(fmaf(a.x, xv, bb.x));
        const float ky = softplus_f(fmaf(a.y, xv, bb.y));
        const float2 c  = __ldg(wq + VOFF2 + s * 8);
        const float2 d  = __ldg(bq + VOFF2 + s * 8);
        const float vx = fmaf(c.x, xv, d.x);
        const float vy = fmaf(c.y, xv, d.y);
        z0 += kx; z1 += ky;

        const int buf = s & 1;
        *(float2*)&kst[buf][g][sub][2 * hl] = make_float2(kx, ky);
        __syncwarp();
        const float4* kv = (const float4*)kst[buf][g][sub];
        const float4 K0 = kv[0], K1 = kv[1], K2 = kv[2], K3 = kv[3];
        const float kk[16] = {K0.x,K0.y,K0.z,K0.w, K1.x,K1.y,K1.z,K1.w,
                              K2.x,K2.y,K2.z,K2.w, K3.x,K3.y,K3.z,K3.w};
#pragma unroll
        for (int i = 0; i < 16; i++) {
            S0[i] = fmaf(kk[i], vx, S0[i]);
            S1[i] = fmaf(kk[i], vy, S1[i]);
        }
    }

    // chunk sums -> global ([b][chunk][i][c] layout), z -> smem
    {
        const long pb = ((long)(chain * SPLIT + seg) * CHUNKS + g) * 256;
#pragma unroll
        for (int i = 0; i < 16; i++)
            *(float2*)&g_prefS[pb + i * 16 + 2 * hl] = make_float2(S0[i], S1[i]);
    }
    *(float2*)&sZ[g][sub][2 * hl] = make_float2(z0, z1);
    __syncthreads();

    // in-place exclusive scan over chunks (L2-hot); all 4 batch subs
    // (g_totS/g_totZ get the INCLUSIVE segment total)
    {
        const int i = tid >> 4, c = tid & 15;
#pragma unroll
        for (int sub2 = 0; sub2 < 4; sub2++) {
            const int chain2 = (quad * 4 + sub2) * NHEAD + head;
            const long base = ((long)(chain2 * SPLIT + seg) * CHUNKS) * 256
                            + i * 16 + c;
            float run = 0.f;
#pragma unroll
            for (int gg = 0; gg < CHUNKS; gg++) {
                const float t = g_prefS[base + gg * 256];
                g_prefS[base + gg * 256] = run;
                run += t;
            }
            g_totS[(long)(chain2 * SPLIT + seg) * 256 + i * 16 + c] = run;
        }
    }
    if (tid < 64) {
        const int sub2 = (tid >> 4) & 3, i2 = tid & 15;
        const int chain2 = (quad * 4 + sub2) * NHEAD + head;
        const long bz = (long)(chain2 * SPLIT + seg) * CHUNKS * 16 + i2;
        float rz = 0.f;
#pragma unroll
        for (int gg = 0; gg < CHUNKS; gg++) {
            g_prefZ[bz + gg * 16] = rz;
            rz += sZ[gg][sub2][i2];
        }
        g_totZ[(long)(chain2 * SPLIT + seg) * 16 + i2] = rz;
    }
}

// ---------------------------------------------------------------------------
// K2: batch-quad rescan from prefix state with q; emit params (heads 0-2 ->
// scratch) or e-summed shifted outputs (heads 3-4 -> d_out).
// Prologue sums inclusive totals of segments 0..seg-1 (scan_b eliminated).
// ---------------------------------------------------------------------------
__global__ __launch_bounds__(256, 3) void scan_c(
    const float* __restrict__ x,
    const float* __restrict__ ew,
    const float* __restrict__ eb,
    const float* __restrict__ ind_out_b,
    const float* __restrict__ ind_res_w,
    float* __restrict__ out)
{
    __shared__ __align__(16) float st[2][CHUNKS][4][32];  // [buf][chunk][sub][k|q]

    const int b    = blockIdx.x;
    const int quad = b / (NHEAD * SPLIT);
    const int rem  = b % (NHEAD * SPLIT);
    const int seg  = rem / NHEAD;
    const int head = rem % NHEAD;
    const int tid  = threadIdx.x;
    const int g    = tid >> 5;
    const int sub  = (tid >> 3) & 3;
    const int hl   = tid & 7;

    const int n     = quad * 4 + sub;
    const int chain = n * NHEAD + head;
    const float* xw = x + (long)n * S_LEN;
    const int pos0  = seg * SEG_LEN + g * CLEN;

    const long qbase = (long)head * S_LEN * 8 + (long)pos0 * 8 + hl;
    const float2* wq = (const float2*)ew + qbase;
    const float2* bq = (const float2*)eb + qbase;

    // prefix state = chunk prefix + sum of preceding segments' totals
    float S0[16], S1[16], z0, z1;
    {
        const long pb = ((long)(chain * SPLIT + seg) * CHUNKS + g) * 256;
#pragma unroll
        for (int i = 0; i < 16; i++) {
            const float2 p = *(const float2*)&g_prefS[pb + i * 16 + 2 * hl];
            S0[i] = p.x; S1[i] = p.y;
        }
        const float2 pz = *(const float2*)&g_prefZ[
            ((long)(chain * SPLIT + seg) * CHUNKS + g) * 16 + 2 * hl];
        z0 = pz.x; z1 = pz.y;
        for (int ss = 0; ss < seg; ss++) {
            const long tb = (long)(chain * SPLIT + ss) * 256;
#pragma unroll
            for (int i = 0; i < 16; i++) {
                const float2 t = *(const float2*)&g_totS[tb + i * 16 + 2 * hl];
                S0[i] += t.x; S1[i] += t.y;
            }
            const float2 tz = *(const float2*)&g_totZ[
                (long)(chain * SPLIT + ss) * 16 + 2 * hl];
            z0 += tz.x; z1 += tz.y;
        }
    }

    const bool isInner = (head < 3);
    float* pdst = nullptr;
    float* odst = nullptr;
    if (isInner) {
        pdst = g_params + ((long)(n * 3 + head) * S_LEN) * EDIM;
    } else {
        const long base = (long)3 * NBATCH * S_LEN * EDIM
                        + (long)(head - 3) * NBATCH * S_LEN;
        odst = out + base + (long)n * S_LEN;
        if (g == 0 && hl == 0 && seg == 0)
            odst[0] = (head == 3) ? ind_out_b[0] : ind_res_w[0];
    }

    for (int s = 0; s < CLEN; s++) {
        const int pos = pos0 + s;
        const float xv = __ldg(xw + pos);
        float2 a, c;
        a = __ldg(wq + s * 8);         c = __ldg(bq + s * 8);
        const float qx = softplus_f(fmaf(a.x, xv, c.x));
        const float qy = softplus_f(fmaf(a.y, xv, c.y));
        a = __ldg(wq + KOFF2 + s * 8); c = __ldg(bq + KOFF2 + s * 8);
        const float kx = softplus_f(fmaf(a.x, xv, c.x));
        const float ky = softplus_f(fmaf(a.y, xv, c.y));
        a = __ldg(wq + VOFF2 + s * 8); c = __ldg(bq + VOFF2 + s * 8);
        const float vx = fmaf(a.x, xv, c.x);
        const float vy = fmaf(a.y, xv, c.y);

        z0 += kx; z1 += ky;

        const int buf = s & 1;
        *(float2*)&st[buf][g][sub][2 * hl]      = make_float2(kx, ky);
        *(float2*)&st[buf][g][sub][16 + 2 * hl] = make_float2(qx, qy);
        __syncwarp();

        float dp = fmaf(qx, z0, qy * z1);
        dp += __shfl_xor_sync(0xffffffffu, dp, 1, 8);
        dp += __shfl_xor_sync(0xffffffffu, dp, 2, 8);
        dp += __shfl_xor_sync(0xffffffffu, dp, 4, 8);

        const float4* kv = (const float4*)&st[buf][g][sub][0];
        const float4* qv = (const float4*)&st[buf][g][sub][16];
        float num0 = 0.f, num1 = 0.f;
#pragma unroll
        for (int q4 = 0; q4 < 4; q4++) {
            const float4 K = kv[q4];
            const float4 Q = qv[q4];
            S0[4*q4+0] = fmaf(K.x, vx, S0[4*q4+0]); num0 = fmaf(Q.x, S0[4*q4+0], num0);
            S0[4*q4+1] = fmaf(K.y, vx, S0[4*q4+1]); num0 = fmaf(Q.y, S0[4*q4+1], num0);
            S0[4*q4+2] = fmaf(K.z, vx, S0[4*q4+2]); num0 = fmaf(Q.z, S0[4*q4+2], num0);
            S0[4*q4+3] = fmaf(K.w, vx, S0[4*q4+3]); num0 = fmaf(Q.w, S0[4*q4+3], num0);
            S1[4*q4+0] = fmaf(K.x, vy, S1[4*q4+0]); num1 = fmaf(Q.x, S1[4*q4+0], num1);
            S1[4*q4+1] = fmaf(K.y, vy, S1[4*q4+1]); num1 = fmaf(Q.y, S1[4*q4+1], num1);
            S1[4*q4+2] = fmaf(K.z, vy, S1[4*q4+2]); num1 = fmaf(Q.z, S1[4*q4+2], num1);
            S1[4*q4+3] = fmaf(K.w, vy, S1[4*q4+3]); num1 = fmaf(Q.w, S1[4*q4+3], num1);
        }
        const float r = __fdividef(1.0f, dp);
        const float p0 = num0 * r, p1 = num1 * r;

        if (isInner) {
            *(float2*)&pdst[(long)pos * EDIM + 2 * hl] = make_float2(p0, p1);
        } else {
            float tot = p0 + p1;
            tot += __shfl_xor_sync(0xffffffffu, tot, 1, 8);
            tot += __shfl_xor_sync(0xffffffffu, tot, 2, 8);
            tot += __shfl_xor_sync(0xffffffffu, tot, 4, 8);
            if (hl == 0 && pos + 1 < S_LEN)
                odst[pos + 1] = tot;
        }
    }
}

// ---------------------------------------------------------------------------
// K3: per-position MLP for heads 0..2 on shifted params.
// 2 positions per thread (pos, pos+1536) sharing every weight load.
// ---------------------------------------------------------------------------
__global__ __launch_bounds__(128, 5) void mlp_kernel(
    const float* __restrict__ ind_in_w,
    const float* __restrict__ ind_in_b,
    const float* __restrict__ ind_out_w,
    const float* __restrict__ fc1_w,
    const float* __restrict__ fc1_b,
    const float* __restrict__ fc2_w,
    const float* __restrict__ fc2_b,
    float* __restrict__ out)
{
    __shared__ __align__(16) float w1[32 * 16];
    __shared__ __align__(16) float w2t[32][16];   // transposed: [o][e]
    __shared__ float b1[32];
    __shared__ float b2[16];

    const int tid = threadIdx.x;
    for (int i = tid; i < 512; i += 128) w1[i] = fc1_w[i];
    for (int i = tid; i < 512; i += 128) {
        const int p = i >> 5, o = i & 31;   // fc2_w is [E][2E] row-major
        w2t[o][p] = fc2_w[i];
    }
    if (tid < 32) b1[tid] = fc1_b[tid];
    if (tid < 16) b2[tid] = fc2_b[tid];
    __syncthreads();

    const int HALF = S_LEN / 2;                  // 1536
    const int t    = blockIdx.x * 128 + tid;     // 0 .. 147455
    const int n    = t / (3 * HALF);
    const int r    = t - n * (3 * HALF);
    const int tt   = r / HALF;
    const int posA = r - tt * HALF;
    const int posB = posA + HALF;

    const float* gp = g_params + (long)(n * 3 + tt) * S_LEN * EDIM;

    float pA[16], pB[16];
    if (posA == 0) {
#pragma unroll
        for (int e = 0; e < 16; e++) {
            pA[e] = (tt == 0) ? softplus_f(ind_in_w[e])
                  : (tt == 1) ? ind_in_b[e]
                              : ind_out_w[e];
        }
    } else {
        const float4* src = (const float4*)(gp + (long)(posA - 1) * EDIM);
        const float4 a = src[0], b = src[1], c = src[2], d = src[3];
        pA[0]=a.x; pA[1]=a.y; pA[2]=a.z; pA[3]=a.w;
        pA[4]=b.x; pA[5]=b.y; pA[6]=b.z; pA[7]=b.w;
        pA[8]=c.x; pA[9]=c.y; pA[10]=c.z; pA[11]=c.w;
        pA[12]=d.x; pA[13]=d.y; pA[14]=d.z; pA[15]=d.w;
    }
    {
        const float4* src = (const float4*)(gp + (long)(posB - 1) * EDIM);
        const float4 a = src[0], b = src[1], c = src[2], d = src[3];
        pB[0]=a.x; pB[1]=a.y; pB[2]=a.z; pB[3]=a.w;
        pB[4]=b.x; pB[5]=b.y; pB[6]=b.z; pB[7]=b.w;
        pB[8]=c.x; pB[9]=c.y; pB[10]=c.z; pB[11]=c.w;
        pB[12]=d.x; pB[13]=d.y; pB[14]=d.z; pB[15]=d.w;
    }

    float accA[16], accB[16];
#pragma unroll
    for (int e = 0; e < 16; e++) { accA[e] = b2[e]; accB[e] = b2[e]; }

#pragma unroll
    for (int o = 0; o < 32; o++) {
        const float4* w1p = (const float4*)&w1[o * 16];
        const float4 W0 = w1p[0], W1 = w1p[1], W2 = w1p[2], W3 = w1p[3];
        float hA0 = fmaf(pA[0], W0.x, 0.f),  hA1 = fmaf(pA[1], W0.y, 0.f);
        float hB0 = fmaf(pB[0], W0.x, 0.f),  hB1 = fmaf(pB[1], W0.y, 0.f);
        hA0 = fmaf(pA[2], W0.z, hA0); hA1 = fmaf(pA[3], W0.w, hA1);
        hB0 = fmaf(pB[2], W0.z, hB0); hB1 = fmaf(pB[3], W0.w, hB1);
        hA0 = fmaf(pA[4], W1.x, hA0); hA1 = fmaf(pA[5], W1.y, hA1);
        hB0 = fmaf(pB[4], W1.x, hB0); hB1 = fmaf(pB[5], W1.y, hB1);
        hA0 = fmaf(pA[6], W1.z, hA0); hA1 = fmaf(pA[7], W1.w, hA1);
        hB0 = fmaf(pB[6], W1.z, hB0); hB1 = fmaf(pB[7], W1.w, hB1);
        hA0 = fmaf(pA[8], W2.x, hA0); hA1 = fmaf(pA[9], W2.y, hA1);
        hB0 = fmaf(pB[8], W2.x, hB0); hB1 = fmaf(pB[9], W2.y, hB1);
        hA0 = fmaf(pA[10], W2.z, hA0); hA1 = fmaf(pA[11], W2.w, hA1);
        hB0 = fmaf(pB[10], W2.z, hB0); hB1 = fmaf(pB[11], W2.w, hB1);
        hA0 = fmaf(pA[12], W3.x, hA0); hA1 = fmaf(pA[13], W3.y, hA1);
        hB0 = fmaf(pB[12], W3.x, hB0); hB1 = fmaf(pB[13], W3.y, hB1);
        hA0 = fmaf(pA[14], W3.z, hA0); hA1 = fmaf(pA[15], W3.w, hA1);
        hB0 = fmaf(pB[14], W3.z, hB0); hB1 = fmaf(pB[15], W3.w, hB1);

        const float hA = fmaxf(hA0 + hA1 + b1[o], 0.0f);
        const float hB = fmaxf(hB0 + hB1 + b1[o], 0.0f);

        const float4* w2p = (const float4*)&w2t[o][0];
        const float4 V0 = w2p[0], V1 = w2p[1], V2 = w2p[2], V3 = w2p[3];
        accA[0] = fmaf(hA, V0.x, accA[0]);  accB[0] = fmaf(hB, V0.x, accB[0]);
        accA[1] = fmaf(hA, V0.y, accA[1]);  accB[1] = fmaf(hB, V0.y, accB[1]);
        accA[2] = fmaf(hA, V0.z, accA[2]);  accB[2] = fmaf(hB, V0.z, accB[2]);
        accA[3] = fmaf(hA, V0.w, accA[3]);  accB[3] = fmaf(hB, V0.w, accB[3]);
        accA[4] = fmaf(hA, V1.x, accA[4]);  accB[4] = fmaf(hB, V1.x, accB[4]);
        accA[5] = fmaf(hA, V1.y, accA[5]);  accB[5] = fmaf(hB, V1.y, accB[5]);
        accA[6] = fmaf(hA, V1.z, accA[6]);  accB[6] = fmaf(hB, V1.z, accB[6]);
        accA[7] = fmaf(hA, V1.w, accA[7]);  accB[7] = fmaf(hB, V1.w, accB[7]);
        accA[8] = fmaf(hA, V2.x, accA[8]);  accB[8] = fmaf(hB, V2.x, accB[8]);
        accA[9] = fmaf(hA, V2.y, accA[9]);  accB[9] = fmaf(hB, V2.y, accB[9]);
        accA[10] = fmaf(hA, V2.z, accA[10]); accB[10] = fmaf(hB, V2.z, accB[10]);
        accA[11] = fmaf(hA, V2.w, accA[11]); accB[11] = fmaf(hB, V2.w, accB[11]);
        accA[12] = fmaf(hA, V3.x, accA[12]); accB[12] = fmaf(hB, V3.x, accB[12]);
        accA[13] = fmaf(hA, V3.y, accA[13]); accB[13] = fmaf(hB, V3.y, accB[13]);
        accA[14] = fmaf(hA, V3.z, accA[14]); accB[14] = fmaf(hB, V3.z, accB[14]);
        accA[15] = fmaf(hA, V3.w, accA[15]); accB[15] = fmaf(hB, V3.w, accB[15]);
    }

    if (tt == 0) {   // in_proj_weight gets a final softplus
#pragma unroll
        for (int e = 0; e < 16; e++) {
            accA[e] = softplus_f(accA[e]);
            accB[e] = softplus_f(accB[e]);
        }
    }

    float* dbase = out + ((long)tt * NBATCH + n) * S_LEN * EDIM;
    float4* dA = (float4*)(dbase + (long)posA * EDIM);
    dA[0] = make_float4(accA[0],  accA[1],  accA[2],  accA[3]);
    dA[1] = make_float4(accA[4],  accA[5],  accA[6],  accA[7]);
    dA[2] = make_float4(accA[8],  accA[9],  accA[10], accA[11]);
    dA[3] = make_float4(accA[12], accA[13], accA[14], accA[15]);
    float4* dB = (float4*)(dbase + (long)posB * EDIM);
    dB[0] = make_float4(accB[0],  accB[1],  accB[2],  accB[3]);
    dB[1] = make_float4(accB[4],  accB[5],  accB[6],  accB[7]);
    dB[2] = make_float4(accB[8],  accB[9],  accB[10], accB[11]);
    dB[3] = make_float4(accB[12], accB[13], accB[14], accB[15]);
}

// ---------------------------------------------------------------------------
extern "C" void kernel_launch(void* const* d_in, const int* in_sizes, int n_in,
                              void* d_out, int out_size)
{
    const float* x         = (const float*)d_in[0];
    const float* ew        = (const float*)d_in[1];
    const float* eb        = (const float*)d_in[2];
    const float* ind_in_w  = (const float*)d_in[3];
    const float* ind_in_b  = (const float*)d_in[4];
    const float* ind_out_w = (const float*)d_in[5];
    const float* ind_out_b = (const float*)d_in[6];
    const float* ind_res_w = (const float*)d_in[7];
    const float* fc1_w     = (const float*)d_in[8];
    const float* fc1_b     = (const float*)d_in[9];
    const float* fc2_w     = (const float*)d_in[10];
    const float* fc2_b     = (const float*)d_in[11];
    float* out = (float*)d_out;

    scan_a<<<NQUAD * NHEAD * SPLIT, 256>>>(x, ew, eb);
    scan_c<<<NQUAD * NHEAD * SPLIT, 256>>>(x, ew, eb, ind_out_b, ind_res_w, out);
    mlp_kernel<<<(NBATCH * 3 * (S_LEN / 2)) / 128, 128>>>(
        ind_in_w, ind_in_b, ind_out_w, fc1_w, fc1_b, fc2_w, fc2_b, out);
}

// round 12
// speedup vs baseline: 1.2892x; 1.2892x over previous
#include <cuda_runtime.h>

#define S_LEN   3072
#define EDIM    16
#define NHEAD   5
#define NBATCH  32
#define NCHAIN  (NBATCH * NHEAD)   // 160
#define SPLIT   16
#define SEG_LEN (S_LEN / SPLIT)    // 192
#define CHUNKS  8
#define CLEN    (SEG_LEN / CHUNKS) // 24
#define NQUAD   (NBATCH / 4)       // 8

// q->k and q->v offsets in float2 units (folded into LDG immediates)
#define KOFF2 (NHEAD * S_LEN * 8)
#define VOFF2 (2 * NHEAD * S_LEN * 8)

// scratch for params of heads 0..2 (inner): [N][3][S_LEN][E]
__device__ float g_params[(long)NBATCH * 3 * S_LEN * EDIM];
// inner-head chunk prefixes: [chain*SPLIT+seg][chunk][i][c]
__device__ float g_prefS[(long)NCHAIN * SPLIT * CHUNKS * 256];
__device__ float g_prefZ[(long)NCHAIN * SPLIT * CHUNKS * 16];
// outer-head t = cumsum(k * sum_j v_j): same layout as z
__device__ float g_prefT[(long)NCHAIN * SPLIT * CHUNKS * 16];
// per-segment totals (inclusive from scan_a; scan_b makes them exclusive)
__device__ float g_totS [(long)NCHAIN * SPLIT * 256];
__device__ float g_totZ [(long)NCHAIN * SPLIT * 16];
__device__ float g_totT [(long)NCHAIN * SPLIT * 16];

__device__ __forceinline__ float softplus_f(float x) {
    // all args here are small (|x| < ~5): unclamped fast form is exact enough
    return __logf(1.0f + __expf(x));
}

// ---------------------------------------------------------------------------
// K1: batch-quad chunk sums + in-segment exclusive prefix.
// grid = NQUAD*SPLIT*NHEAD = 640, block = 256 = 8 chunks x (4 batches x 8).
// Inner heads (0-2): full 16x16 S state. Outer heads (3-4): only z (16) and
// t = cumsum(k * vsum) (16) are needed, since the output is sum_j params_j.
// ---------------------------------------------------------------------------
__global__ __launch_bounds__(256, 3) void scan_a(
    const float* __restrict__ x,
    const float* __restrict__ ew,
    const float* __restrict__ eb)
{
    __shared__ __align__(16) float kst[2][CHUNKS][4][16];
    __shared__ float sZ[CHUNKS][4][16];
    __shared__ float sT[CHUNKS][4][16];

    const int b    = blockIdx.x;
    const int quad = b / (NHEAD * SPLIT);
    const int rem  = b % (NHEAD * SPLIT);
    const int seg  = rem / NHEAD;
    const int head = rem % NHEAD;
    const int tid  = threadIdx.x;
    const int g    = tid >> 5;          // chunk 0..7
    const int sub  = (tid >> 3) & 3;    // batch within quad
    const int hl   = tid & 7;

    const int n     = quad * 4 + sub;
    const int chain = n * NHEAD + head;
    const float* xw = x + (long)n * S_LEN;
    const int pos0  = seg * SEG_LEN + g * CLEN;

    const long qbase = (long)head * S_LEN * 8 + (long)pos0 * 8 + hl;
    const float2* wq = (const float2*)ew + qbase;
    const float2* bq = (const float2*)eb + qbase;

    if (head < 3) {
        // ---------------- inner heads: full S state ----------------
        float S0[16], S1[16];
#pragma unroll
        for (int i = 0; i < 16; i++) { S0[i] = 0.f; S1[i] = 0.f; }
        float z0 = 0.f, z1 = 0.f;

        for (int s = 0; s < CLEN; s++) {
            const float xv = __ldg(xw + pos0 + s);
            const float2 a  = __ldg(wq + KOFF2 + s * 8);
            const float2 bb = __ldg(bq + KOFF2 + s * 8);
            const float kx = softplus_f(fmaf(a.x, xv, bb.x));
            const float ky = softplus_f(fmaf(a.y, xv, bb.y));
            const float2 c  = __ldg(wq + VOFF2 + s * 8);
            const float2 d  = __ldg(bq + VOFF2 + s * 8);
            const float vx = fmaf(c.x, xv, d.x);
            const float vy = fmaf(c.y, xv, d.y);
            z0 += kx; z1 += ky;

            const int buf = s & 1;
            *(float2*)&kst[buf][g][sub][2 * hl] = make_float2(kx, ky);
            __syncwarp();
            const float4* kv = (const float4*)kst[buf][g][sub];
            const float4 K0 = kv[0], K1 = kv[1], K2 = kv[2], K3 = kv[3];
            const float kk[16] = {K0.x,K0.y,K0.z,K0.w, K1.x,K1.y,K1.z,K1.w,
                                  K2.x,K2.y,K2.z,K2.w, K3.x,K3.y,K3.z,K3.w};
#pragma unroll
            for (int i = 0; i < 16; i++) {
                S0[i] = fmaf(kk[i], vx, S0[i]);
                S1[i] = fmaf(kk[i], vy, S1[i]);
            }
        }

        // chunk sums -> global ([b][chunk][i][c] layout), z -> smem
        {
            const long pb = ((long)(chain * SPLIT + seg) * CHUNKS + g) * 256;
#pragma unroll
            for (int i = 0; i < 16; i++)
                *(float2*)&g_prefS[pb + i * 16 + 2 * hl] = make_float2(S0[i], S1[i]);
        }
        *(float2*)&sZ[g][sub][2 * hl] = make_float2(z0, z1);
        __syncthreads();

        // in-place exclusive scan over chunks (L2-hot); all 4 batch subs
        {
            const int i = tid >> 4, c = tid & 15;
#pragma unroll
            for (int sub2 = 0; sub2 < 4; sub2++) {
                const int chain2 = (quad * 4 + sub2) * NHEAD + head;
                const long base = ((long)(chain2 * SPLIT + seg) * CHUNKS) * 256
                                + i * 16 + c;
                float run = 0.f;
#pragma unroll
                for (int gg = 0; gg < CHUNKS; gg++) {
                    const float t = g_prefS[base + gg * 256];
                    g_prefS[base + gg * 256] = run;
                    run += t;
                }
                g_totS[(long)(chain2 * SPLIT + seg) * 256 + i * 16 + c] = run;
            }
        }
        if (tid < 64) {
            const int sub2 = (tid >> 4) & 3, i2 = tid & 15;
            const int chain2 = (quad * 4 + sub2) * NHEAD + head;
            const long bz = (long)(chain2 * SPLIT + seg) * CHUNKS * 16 + i2;
            float rz = 0.f;
#pragma unroll
            for (int gg = 0; gg < CHUNKS; gg++) {
                g_prefZ[bz + gg * 16] = rz;
                rz += sZ[gg][sub2][i2];
            }
            g_totZ[(long)(chain2 * SPLIT + seg) * 16 + i2] = rz;
        }
    } else {
        // ---------------- outer heads: only z and t ----------------
        float z0 = 0.f, z1 = 0.f, t0 = 0.f, t1 = 0.f;

        for (int s = 0; s < CLEN; s++) {
            const float xv = __ldg(xw + pos0 + s);
            const float2 a  = __ldg(wq + KOFF2 + s * 8);
            const float2 bb = __ldg(bq + KOFF2 + s * 8);
            const float kx = softplus_f(fmaf(a.x, xv, bb.x));
            const float ky = softplus_f(fmaf(a.y, xv, bb.y));
            const float2 c  = __ldg(wq + VOFF2 + s * 8);
            const float2 d  = __ldg(bq + VOFF2 + s * 8);
            const float vx = fmaf(c.x, xv, d.x);
            const float vy = fmaf(c.y, xv, d.y);
            float vs = vx + vy;
            vs += __shfl_xor_sync(0xffffffffu, vs, 1, 8);
            vs += __shfl_xor_sync(0xffffffffu, vs, 2, 8);
            vs += __shfl_xor_sync(0xffffffffu, vs, 4, 8);
            z0 += kx; z1 += ky;
            t0 = fmaf(kx, vs, t0);
            t1 = fmaf(ky, vs, t1);
        }

        *(float2*)&sZ[g][sub][2 * hl] = make_float2(z0, z1);
        *(float2*)&sT[g][sub][2 * hl] = make_float2(t0, t1);
        __syncthreads();

        if (tid < 64) {
            const int sub2 = (tid >> 4) & 3, i2 = tid & 15;
            const int chain2 = (quad * 4 + sub2) * NHEAD + head;
            const long bz = (long)(chain2 * SPLIT + seg) * CHUNKS * 16 + i2;
            float rz = 0.f;
#pragma unroll
            for (int gg = 0; gg < CHUNKS; gg++) {
                g_prefZ[bz + gg * 16] = rz;
                rz += sZ[gg][sub2][i2];
            }
            g_totZ[(long)(chain2 * SPLIT + seg) * 16 + i2] = rz;
        } else if (tid < 128) {
            const int sub2 = (tid >> 4) & 3, i2 = tid & 15;
            const int chain2 = (quad * 4 + sub2) * NHEAD + head;
            const long bt = (long)(chain2 * SPLIT + seg) * CHUNKS * 16 + i2;
            float rt = 0.f;
#pragma unroll
            for (int gg = 0; gg < CHUNKS; gg++) {
                g_prefT[bt + gg * 16] = rt;
                rt += sT[gg][sub2][i2];
            }
            g_totT[(long)(chain2 * SPLIT + seg) * 16 + i2] = rt;
        }
    }
}

// ---------------------------------------------------------------------------
// K2: exclusive prefix of segment totals across SPLIT segments of each chain
// (in place). grid = 160, block = 288.  (S entries for outer chains are
// garbage-scanned; harmless.)
// ---------------------------------------------------------------------------
__global__ void scan_b()
{
    const int chain = blockIdx.x;
    const int t = threadIdx.x;
    if (t < 256) {
        float run = 0.f;
#pragma unroll
        for (int s = 0; s < SPLIT; s++) {
            const long idx = ((long)chain * SPLIT + s) * 256 + t;
            const float v = g_totS[idx]; g_totS[idx] = run; run += v;
        }
    } else if (t < 272) {
        const int i = t - 256;
        float run = 0.f;
#pragma unroll
        for (int s = 0; s < SPLIT; s++) {
            const long idx = ((long)chain * SPLIT + s) * 16 + i;
            const float v = g_totZ[idx]; g_totZ[idx] = run; run += v;
        }
    } else {
        const int i = t - 272;
        float run = 0.f;
#pragma unroll
        for (int s = 0; s < SPLIT; s++) {
            const long idx = ((long)chain * SPLIT + s) * 16 + i;
            const float v = g_totT[idx]; g_totT[idx] = run; run += v;
        }
    }
}

// ---------------------------------------------------------------------------
// K3: batch-quad rescan from prefix state with q.
// Inner heads: full S rescan -> params scratch. Outer heads: light t/z
// rescan -> e-summed shifted output directly.
// ---------------------------------------------------------------------------
__global__ __launch_bounds__(256, 3) void scan_c(
    const float* __restrict__ x,
    const float* __restrict__ ew,
    const float* __restrict__ eb,
    const float* __restrict__ ind_out_b,
    const float* __restrict__ ind_res_w,
    float* __restrict__ out)
{
    __shared__ __align__(16) float st[2][CHUNKS][4][32];  // [buf][chunk][sub][k|q]

    const int b    = blockIdx.x;
    const int quad = b / (NHEAD * SPLIT);
    const int rem  = b % (NHEAD * SPLIT);
    const int seg  = rem / NHEAD;
    const int head = rem % NHEAD;
    const int tid  = threadIdx.x;
    const int g    = tid >> 5;
    const int sub  = (tid >> 3) & 3;
    const int hl   = tid & 7;

    const int n     = quad * 4 + sub;
    const int chain = n * NHEAD + head;
    const float* xw = x + (long)n * S_LEN;
    const int pos0  = seg * SEG_LEN + g * CLEN;

    const long qbase = (long)head * S_LEN * 8 + (long)pos0 * 8 + hl;
    const float2* wq = (const float2*)ew + qbase;
    const float2* bq = (const float2*)eb + qbase;

    if (head < 3) {
        // ---------------- inner heads ----------------
        float S0[16], S1[16], z0, z1;
        {
            const long pb = ((long)(chain * SPLIT + seg) * CHUNKS + g) * 256;
            const long tb = (long)(chain * SPLIT + seg) * 256;
#pragma unroll
            for (int i = 0; i < 16; i++) {
                const float2 p = *(const float2*)&g_prefS[pb + i * 16 + 2 * hl];
                const float2 t = *(const float2*)&g_totS[tb + i * 16 + 2 * hl];
                S0[i] = p.x + t.x; S1[i] = p.y + t.y;
            }
            const float2 pz = *(const float2*)&g_prefZ[
                ((long)(chain * SPLIT + seg) * CHUNKS + g) * 16 + 2 * hl];
            const float2 tz = *(const float2*)&g_totZ[
                (long)(chain * SPLIT + seg) * 16 + 2 * hl];
            z0 = pz.x + tz.x; z1 = pz.y + tz.y;
        }

        float* pdst = g_params + ((long)(n * 3 + head) * S_LEN) * EDIM;

        for (int s = 0; s < CLEN; s++) {
            const int pos = pos0 + s;
            const float xv = __ldg(xw + pos);
            float2 a, c;
            a = __ldg(wq + s * 8);         c = __ldg(bq + s * 8);
            const float qx = softplus_f(fmaf(a.x, xv, c.x));
            const float qy = softplus_f(fmaf(a.y, xv, c.y));
            a = __ldg(wq + KOFF2 + s * 8); c = __ldg(bq + KOFF2 + s * 8);
            const float kx = softplus_f(fmaf(a.x, xv, c.x));
            const float ky = softplus_f(fmaf(a.y, xv, c.y));
            a = __ldg(wq + VOFF2 + s * 8); c = __ldg(bq + VOFF2 + s * 8);
            const float vx = fmaf(a.x, xv, c.x);
            const float vy = fmaf(a.y, xv, c.y);

            z0 += kx; z1 += ky;

            const int buf = s & 1;
            *(float2*)&st[buf][g][sub][2 * hl]      = make_float2(kx, ky);
            *(float2*)&st[buf][g][sub][16 + 2 * hl] = make_float2(qx, qy);
            __syncwarp();

            float dp = fmaf(qx, z0, qy * z1);
            dp += __shfl_xor_sync(0xffffffffu, dp, 1, 8);
            dp += __shfl_xor_sync(0xffffffffu, dp, 2, 8);
            dp += __shfl_xor_sync(0xffffffffu, dp, 4, 8);

            const float4* kv = (const float4*)&st[buf][g][sub][0];
            const float4* qv = (const float4*)&st[buf][g][sub][16];
            float num0 = 0.f, num1 = 0.f;
#pragma unroll
            for (int q4 = 0; q4 < 4; q4++) {
                const float4 K = kv[q4];
                const float4 Q = qv[q4];
                S0[4*q4+0] = fmaf(K.x, vx, S0[4*q4+0]); num0 = fmaf(Q.x, S0[4*q4+0], num0);
                S0[4*q4+1] = fmaf(K.y, vx, S0[4*q4+1]); num0 = fmaf(Q.y, S0[4*q4+1], num0);
                S0[4*q4+2] = fmaf(K.z, vx, S0[4*q4+2]); num0 = fmaf(Q.z, S0[4*q4+2], num0);
                S0[4*q4+3] = fmaf(K.w, vx, S0[4*q4+3]); num0 = fmaf(Q.w, S0[4*q4+3], num0);
                S1[4*q4+0] = fmaf(K.x, vy, S1[4*q4+0]); num1 = fmaf(Q.x, S1[4*q4+0], num1);
                S1[4*q4+1] = fmaf(K.y, vy, S1[4*q4+1]); num1 = fmaf(Q.y, S1[4*q4+1], num1);
                S1[4*q4+2] = fmaf(K.z, vy, S1[4*q4+2]); num1 = fmaf(Q.z, S1[4*q4+2], num1);
                S1[4*q4+3] = fmaf(K.w, vy, S1[4*q4+3]); num1 = fmaf(Q.w, S1[4*q4+3], num1);
            }
            const float r = __fdividef(1.0f, dp);
            const float p0 = num0 * r, p1 = num1 * r;
            *(float2*)&pdst[(long)pos * EDIM + 2 * hl] = make_float2(p0, p1);
        }
    } else {
        // ---------------- outer heads: light path ----------------
        float z0, z1, t0, t1;
        {
            const long zb = ((long)(chain * SPLIT + seg) * CHUNKS + g) * 16 + 2 * hl;
            const long tb = (long)(chain * SPLIT + seg) * 16 + 2 * hl;
            const float2 pz = *(const float2*)&g_prefZ[zb];
            const float2 tz = *(const float2*)&g_totZ[tb];
            const float2 pt = *(const float2*)&g_prefT[zb];
            const float2 tt = *(const float2*)&g_totT[tb];
            z0 = pz.x + tz.x; z1 = pz.y + tz.y;
            t0 = pt.x + tt.x; t1 = pt.y + tt.y;
        }

        const long base = (long)3 * NBATCH * S_LEN * EDIM
                        + (long)(head - 3) * NBATCH * S_LEN;
        float* odst = out + base + (long)n * S_LEN;
        if (g == 0 && hl == 0 && seg == 0)
            odst[0] = (head == 3) ? ind_out_b[0] : ind_res_w[0];

        for (int s = 0; s < CLEN; s++) {
            const int pos = pos0 + s;
            const float xv = __ldg(xw + pos);
            float2 a, c;
            a = __ldg(wq + s * 8);         c = __ldg(bq + s * 8);
            const float qx = softplus_f(fmaf(a.x, xv, c.x));
            const float qy = softplus_f(fmaf(a.y, xv, c.y));
            a = __ldg(wq + KOFF2 + s * 8); c = __ldg(bq + KOFF2 + s * 8);
            const float kx = softplus_f(fmaf(a.x, xv, c.x));
            const float ky = softplus_f(fmaf(a.y, xv, c.y));
            a = __ldg(wq + VOFF2 + s * 8); c = __ldg(bq + VOFF2 + s * 8);
            const float vx = fmaf(a.x, xv, c.x);
            const float vy = fmaf(a.y, xv, c.y);

            float vs = vx + vy;
            vs += __shfl_xor_sync(0xffffffffu, vs, 1, 8);
            vs += __shfl_xor_sync(0xffffffffu, vs, 2, 8);
            vs += __shfl_xor_sync(0xffffffffu, vs, 4, 8);

            z0 += kx; z1 += ky;
            t0 = fmaf(kx, vs, t0);
            t1 = fmaf(ky, vs, t1);

            float dp = fmaf(qx, z0, qy * z1);
            float nm = fmaf(qx, t0, qy * t1);
            dp += __shfl_xor_sync(0xffffffffu, dp, 1, 8);
            nm += __shfl_xor_sync(0xffffffffu, nm, 1, 8);
            dp += __shfl_xor_sync(0xffffffffu, dp, 2, 8);
            nm += __shfl_xor_sync(0xffffffffu, nm, 2, 8);
            dp += __shfl_xor_sync(0xffffffffu, dp, 4, 8);
            nm += __shfl_xor_sync(0xffffffffu, nm, 4, 8);

            if (hl == 0 && pos + 1 < S_LEN)
                odst[pos + 1] = __fdividef(nm, dp);
        }
    }
}

// ---------------------------------------------------------------------------
// K4: per-position MLP for heads 0..2 on shifted params.
// 2 positions per thread (pos, pos+1536) sharing every weight load.
// ---------------------------------------------------------------------------
__global__ __launch_bounds__(128) void mlp_kernel(
    const float* __restrict__ ind_in_w,
    const float* __restrict__ ind_in_b,
    const float* __restrict__ ind_out_w,
    const float* __restrict__ fc1_w,
    const float* __restrict__ fc1_b,
    const float* __restrict__ fc2_w,
    const float* __restrict__ fc2_b,
    float* __restrict__ out)
{
    __shared__ __align__(16) float w1[32 * 16];
    __shared__ __align__(16) float w2t[32][16];   // transposed: [o][e]
    __shared__ float b1[32];
    __shared__ float b2[16];

    const int tid = threadIdx.x;
    for (int i = tid; i < 512; i += 128) w1[i] = fc1_w[i];
    for (int i = tid; i < 512; i += 128) {
        const int p = i >> 5, o = i & 31;   // fc2_w is [E][2E] row-major
        w2t[o][p] = fc2_w[i];
    }
    if (tid < 32) b1[tid] = fc1_b[tid];
    if (tid < 16) b2[tid] = fc2_b[tid];
    __syncthreads();

    const int HALF = S_LEN / 2;                  // 1536
    const int t    = blockIdx.x * 128 + tid;     // 0 .. 147455
    const int n    = t / (3 * HALF);
    const int r    = t - n * (3 * HALF);
    const int tt   = r / HALF;
    const int posA = r - tt * HALF;
    const int posB = posA + HALF;

    const float* gp = g_params + (long)(n * 3 + tt) * S_LEN * EDIM;

    float pA[16], pB[16];
    if (posA == 0) {
#pragma unroll
        for (int e = 0; e < 16; e++) {
            pA[e] = (tt == 0) ? softplus_f(ind_in_w[e])
                  : (tt == 1) ? ind_in_b[e]
                              : ind_out_w[e];
        }
    } else {
        const float4* src = (const float4*)(gp + (long)(posA - 1) * EDIM);
        const float4 a = src[0], b = src[1], c = src[2], d = src[3];
        pA[0]=a.x; pA[1]=a.y; pA[2]=a.z; pA[3]=a.w;
        pA[4]=b.x; pA[5]=b.y; pA[6]=b.z; pA[7]=b.w;
        pA[8]=c.x; pA[9]=c.y; pA[10]=c.z; pA[11]=c.w;
        pA[12]=d.x; pA[13]=d.y; pA[14]=d.z; pA[15]=d.w;
    }
    {
        const float4* src = (const float4*)(gp + (long)(posB - 1) * EDIM);
        const float4 a = src[0], b = src[1], c = src[2], d = src[3];
        pB[0]=a.x; pB[1]=a.y; pB[2]=a.z; pB[3]=a.w;
        pB[4]=b.x; pB[5]=b.y; pB[6]=b.z; pB[7]=b.w;
        pB[8]=c.x; pB[9]=c.y; pB[10]=c.z; pB[11]=c.w;
        pB[12]=d.x; pB[13]=d.y; pB[14]=d.z; pB[15]=d.w;
    }

    float accA[16], accB[16];
#pragma unroll
    for (int e = 0; e < 16; e++) { accA[e] = b2[e]; accB[e] = b2[e]; }

#pragma unroll
    for (int o = 0; o < 32; o++) {
        const float4* w1p = (const float4*)&w1[o * 16];
        const float4 W0 = w1p[0], W1 = w1p[1], W2 = w1p[2], W3 = w1p[3];
        float hA0 = fmaf(pA[0], W0.x, 0.f),  hA1 = fmaf(pA[1], W0.y, 0.f);
        float hB0 = fmaf(pB[0], W0.x, 0.f),  hB1 = fmaf(pB[1], W0.y, 0.f);
        hA0 = fmaf(pA[2], W0.z, hA0); hA1 = fmaf(pA[3], W0.w, hA1);
        hB0 = fmaf(pB[2], W0.z, hB0); hB1 = fmaf(pB[3], W0.w, hB1);
        hA0 = fmaf(pA[4], W1.x, hA0); hA1 = fmaf(pA[5], W1.y, hA1);
        hB0 = fmaf(pB[4], W1.x, hB0); hB1 = fmaf(pB[5], W1.y, hB1);
        hA0 = fmaf(pA[6], W1.z, hA0); hA1 = fmaf(pA[7], W1.w, hA1);
        hB0 = fmaf(pB[6], W1.z, hB0); hB1 = fmaf(pB[7], W1.w, hB1);
        hA0 = fmaf(pA[8], W2.x, hA0); hA1 = fmaf(pA[9], W2.y, hA1);
        hB0 = fmaf(pB[8], W2.x, hB0); hB1 = fmaf(pB[9], W2.y, hB1);
        hA0 = fmaf(pA[10], W2.z, hA0); hA1 = fmaf(pA[11], W2.w, hA1);
        hB0 = fmaf(pB[10], W2.z, hB0); hB1 = fmaf(pB[11], W2.w, hB1);
        hA0 = fmaf(pA[12], W3.x, hA0); hA1 = fmaf(pA[13], W3.y, hA1);
        hB0 = fmaf(pB[12], W3.x, hB0); hB1 = fmaf(pB[13], W3.y, hB1);
        hA0 = fmaf(pA[14], W3.z, hA0); hA1 = fmaf(pA[15], W3.w, hA1);
        hB0 = fmaf(pB[14], W3.z, hB0); hB1 = fmaf(pB[15], W3.w, hB1);

        const float hA = fmaxf(hA0 + hA1 + b1[o], 0.0f);
        const float hB = fmaxf(hB0 + hB1 + b1[o], 0.0f);

        const float4* w2p = (const float4*)&w2t[o][0];
        const float4 V0 = w2p[0], V1 = w2p[1], V2 = w2p[2], V3 = w2p[3];
        accA[0] = fmaf(hA, V0.x, accA[0]);  accB[0] = fmaf(hB, V0.x, accB[0]);
        accA[1] = fmaf(hA, V0.y, accA[1]);  accB[1] = fmaf(hB, V0.y, accB[1]);
        accA[2] = fmaf(hA, V0.z, accA[2]);  accB[2] = fmaf(hB, V0.z, accB[2]);
        accA[3] = fmaf(hA, V0.w, accA[3]);  accB[3] = fmaf(hB, V0.w, accB[3]);
        accA[4] = fmaf(hA, V1.x, accA[4]);  accB[4] = fmaf(hB, V1.x, accB[4]);
        accA[5] = fmaf(hA, V1.y, accA[5]);  accB[5] = fmaf(hB, V1.y, accB[5]);
        accA[6] = fmaf(hA, V1.z, accA[6]);  accB[6] = fmaf(hB, V1.z, accB[6]);
        accA[7] = fmaf(hA, V1.w, accA[7]);  accB[7] = fmaf(hB, V1.w, accB[7]);
        accA[8] = fmaf(hA, V2.x, accA[8]);  accB[8] = fmaf(hB, V2.x, accB[8]);
        accA[9] = fmaf(hA, V2.y, accA[9]);  accB[9] = fmaf(hB, V2.y, accB[9]);
        accA[10] = fmaf(hA, V2.z, accA[10]); accB[10] = fmaf(hB, V2.z, accB[10]);
        accA[11] = fmaf(hA, V2.w, accA[11]); accB[11] = fmaf(hB, V2.w, accB[11]);
        accA[12] = fmaf(hA, V3.x, accA[12]); accB[12] = fmaf(hB, V3.x, accB[12]);
        accA[13] = fmaf(hA, V3.y, accA[13]); accB[13] = fmaf(hB, V3.y, accB[13]);
        accA[14] = fmaf(hA, V3.z, accA[14]); accB[14] = fmaf(hB, V3.z, accB[14]);
        accA[15] = fmaf(hA, V3.w, accA[15]); accB[15] = fmaf(hB, V3.w, accB[15]);
    }

    if (tt == 0) {   // in_proj_weight gets a final softplus
#pragma unroll
        for (int e = 0; e < 16; e++) {
            accA[e] = softplus_f(accA[e]);
            accB[e] = softplus_f(accB[e]);
        }
    }

    float* dbase = out + ((long)tt * NBATCH + n) * S_LEN * EDIM;
    float4* dA = (float4*)(dbase + (long)posA * EDIM);
    dA[0] = make_float4(accA[0],  accA[1],  accA[2],  accA[3]);
    dA[1] = make_float4(accA[4],  accA[5],  accA[6],  accA[7]);
    dA[2] = make_float4(accA[8],  accA[9],  accA[10], accA[11]);
    dA[3] = make_float4(accA[12], accA[13], accA[14], accA[15]);
    float4* dB = (float4*)(dbase + (long)posB * EDIM);
    dB[0] = make_float4(accB[0],  accB[1],  accB[2],  accB[3]);
    dB[1] = make_float4(accB[4],  accB[5],  accB[6],  accB[7]);
    dB[2] = make_float4(accB[8],  accB[9],  accB[10], accB[11]);
    dB[3] = make_float4(accB[12], accB[13], accB[14], accB[15]);
}

// ---------------------------------------------------------------------------
extern "C" void kernel_launch(void* const* d_in, const int* in_sizes, int n_in,
                              void* d_out, int out_size)
{
    const float* x         = (const float*)d_in[0];
    const float* ew        = (const float*)d_in[1];
    const float* eb        = (const float*)d_in[2];
    const float* ind_in_w  = (const float*)d_in[3];
    const float* ind_in_b  = (const float*)d_in[4];
    const float* ind_out_w = (const float*)d_in[5];
    const float* ind_out_b = (const float*)d_in[6];
    const float* ind_res_w = (const float*)d_in[7];
    const float* fc1_w     = (const float*)d_in[8];
    const float* fc1_b     = (const float*)d_in[9];
    const float* fc2_w     = (const float*)d_in[10];
    const float* fc2_b     = (const float*)d_in[11];
    float* out = (float*)d_out;

    scan_a<<<NQUAD * NHEAD * SPLIT, 256>>>(x, ew, eb);
    scan_b<<<NCHAIN, 288>>>();
    scan_c<<<NQUAD * NHEAD * SPLIT, 256>>>(x, ew, eb, ind_out_b, ind_res_w, out);
    mlp_kernel<<<(NBATCH * 3 * (S_LEN / 2)) / 128, 128>>>(
        ind_in_w, ind_in_b, ind_out_w, fc1_w, fc1_b, fc2_w, fc2_b, out);
}

// round 13
// speedup vs baseline: 1.3135x; 1.0189x over previous
#include <cuda_runtime.h>

#define S_LEN   3072
#define EDIM    16
#define NHEAD   5
#define NBATCH  32
#define NCHAIN  (NBATCH * NHEAD)   // 160
#define SPLIT   16
#define SEG_LEN (S_LEN / SPLIT)    // 192
#define CHUNKS  4
#define CLEN    (SEG_LEN / CHUNKS) // 48
#define NQUAD   (NBATCH / 4)       // 8

// q->k and q->v offsets in float2 units (folded into LDG immediates)
#define KOFF2 (NHEAD * S_LEN * 8)
#define VOFF2 (2 * NHEAD * S_LEN * 8)

// scratch for params of heads 0..2 (inner): [N][3][S_LEN][E]
__device__ float g_params[(long)NBATCH * 3 * S_LEN * EDIM];
// inner-head chunk prefixes: [chain*SPLIT+seg][chunk][i][c]
__device__ float g_prefS[(long)NCHAIN * SPLIT * CHUNKS * 256];
__device__ float g_prefZ[(long)NCHAIN * SPLIT * CHUNKS * 16];
// outer-head t = cumsum(k * sum_j v_j): same layout as z
__device__ float g_prefT[(long)NCHAIN * SPLIT * CHUNKS * 16];
// per-segment totals (inclusive from scan_a; scan_b makes them exclusive)
__device__ float g_totS [(long)NCHAIN * SPLIT * 256];
__device__ float g_totZ [(long)NCHAIN * SPLIT * 16];
__device__ float g_totT [(long)NCHAIN * SPLIT * 16];

__device__ __forceinline__ float softplus_f(float x) {
    // all args here are small (|x| < ~5): unclamped fast form is exact enough
    return __logf(1.0f + __expf(x));
}

// ---------------------------------------------------------------------------
// K1: batch-quad chunk sums + in-segment exclusive prefix.
// grid = NQUAD*SPLIT*NHEAD = 640, block = 128 = 4 chunks x (4 batches x 8).
// 128-thread blocks -> 6 blocks/SM -> 888-block wave capacity -> ONE wave.
// One warp = 1 chunk x 4 batches: all 32 lanes read the SAME 64B weight
// region per array -> 1 L1 wavefront per weight LDG serving 4 batches.
// ---------------------------------------------------------------------------
__global__ __launch_bounds__(128, 6) void scan_a(
    const float* __restrict__ x,
    const float* __restrict__ ew,
    const float* __restrict__ eb)
{
    __shared__ __align__(16) float kst[2][CHUNKS][4][16];
    __shared__ float sZ[CHUNKS][4][16];
    __shared__ float sT[CHUNKS][4][16];

    const int b    = blockIdx.x;
    const int quad = b / (NHEAD * SPLIT);
    const int rem  = b % (NHEAD * SPLIT);
    const int seg  = rem / NHEAD;
    const int head = rem % NHEAD;
    const int tid  = threadIdx.x;
    const int g    = tid >> 5;          // chunk 0..3
    const int sub  = (tid >> 3) & 3;    // batch within quad
    const int hl   = tid & 7;

    const int n     = quad * 4 + sub;
    const int chain = n * NHEAD + head;
    const float* xw = x + (long)n * S_LEN;
    const int pos0  = seg * SEG_LEN + g * CLEN;

    const long qbase = (long)head * S_LEN * 8 + (long)pos0 * 8 + hl;
    const float2* wq = (const float2*)ew + qbase;
    const float2* bq = (const float2*)eb + qbase;

    if (head < 3) {
        // ---------------- inner heads: full S state ----------------
        float S0[16], S1[16];
#pragma unroll
        for (int i = 0; i < 16; i++) { S0[i] = 0.f; S1[i] = 0.f; }
        float z0 = 0.f, z1 = 0.f;

        for (int s = 0; s < CLEN; s++) {
            const float xv = __ldg(xw + pos0 + s);
            const float2 a  = __ldg(wq + KOFF2 + s * 8);
            const float2 bb = __ldg(bq + KOFF2 + s * 8);
            const float kx = softplus_f(fmaf(a.x, xv, bb.x));
            const float ky = softplus_f(fmaf(a.y, xv, bb.y));
            const float2 c  = __ldg(wq + VOFF2 + s * 8);
            const float2 d  = __ldg(bq + VOFF2 + s * 8);
            const float vx = fmaf(c.x, xv, d.x);
            const float vy = fmaf(c.y, xv, d.y);
            z0 += kx; z1 += ky;

            const int buf = s & 1;
            *(float2*)&kst[buf][g][sub][2 * hl] = make_float2(kx, ky);
            __syncwarp();
            const float4* kv = (const float4*)kst[buf][g][sub];
            const float4 K0 = kv[0], K1 = kv[1], K2 = kv[2], K3 = kv[3];
            const float kk[16] = {K0.x,K0.y,K0.z,K0.w, K1.x,K1.y,K1.z,K1.w,
                                  K2.x,K2.y,K2.z,K2.w, K3.x,K3.y,K3.z,K3.w};
#pragma unroll
            for (int i = 0; i < 16; i++) {
                S0[i] = fmaf(kk[i], vx, S0[i]);
                S1[i] = fmaf(kk[i], vy, S1[i]);
            }
        }

        // chunk sums -> global ([b][chunk][i][c] layout), z -> smem
        {
            const long pb = ((long)(chain * SPLIT + seg) * CHUNKS + g) * 256;
#pragma unroll
            for (int i = 0; i < 16; i++)
                *(float2*)&g_prefS[pb + i * 16 + 2 * hl] = make_float2(S0[i], S1[i]);
        }
        *(float2*)&sZ[g][sub][2 * hl] = make_float2(z0, z1);
        __syncthreads();

        // in-place exclusive scan over chunks (L2-hot); 128 thr x 2 entries
#pragma unroll
        for (int e = tid; e < 256; e += 128) {
#pragma unroll
            for (int sub2 = 0; sub2 < 4; sub2++) {
                const int chain2 = (quad * 4 + sub2) * NHEAD + head;
                const long base = ((long)(chain2 * SPLIT + seg) * CHUNKS) * 256 + e;
                float run = 0.f;
#pragma unroll
                for (int gg = 0; gg < CHUNKS; gg++) {
                    const float t = g_prefS[base + gg * 256];
                    g_prefS[base + gg * 256] = run;
                    run += t;
                }
                g_totS[(long)(chain2 * SPLIT + seg) * 256 + e] = run;
            }
        }
        if (tid < 64) {
            const int sub2 = (tid >> 4) & 3, i2 = tid & 15;
            const int chain2 = (quad * 4 + sub2) * NHEAD + head;
            const long bz = (long)(chain2 * SPLIT + seg) * CHUNKS * 16 + i2;
            float rz = 0.f;
#pragma unroll
            for (int gg = 0; gg < CHUNKS; gg++) {
                g_prefZ[bz + gg * 16] = rz;
                rz += sZ[gg][sub2][i2];
            }
            g_totZ[(long)(chain2 * SPLIT + seg) * 16 + i2] = rz;
        }
    } else {
        // ---------------- outer heads: only z and t ----------------
        float z0 = 0.f, z1 = 0.f, t0 = 0.f, t1 = 0.f;

        for (int s = 0; s < CLEN; s++) {
            const float xv = __ldg(xw + pos0 + s);
            const float2 a  = __ldg(wq + KOFF2 + s * 8);
            const float2 bb = __ldg(bq + KOFF2 + s * 8);
            const float kx = softplus_f(fmaf(a.x, xv, bb.x));
            const float ky = softplus_f(fmaf(a.y, xv, bb.y));
            const float2 c  = __ldg(wq + VOFF2 + s * 8);
            const float2 d  = __ldg(bq + VOFF2 + s * 8);
            const float vx = fmaf(c.x, xv, d.x);
            const float vy = fmaf(c.y, xv, d.y);
            float vs = vx + vy;
            vs += __shfl_xor_sync(0xffffffffu, vs, 1, 8);
            vs += __shfl_xor_sync(0xffffffffu, vs, 2, 8);
            vs += __shfl_xor_sync(0xffffffffu, vs, 4, 8);
            z0 += kx; z1 += ky;
            t0 = fmaf(kx, vs, t0);
            t1 = fmaf(ky, vs, t1);
        }

        *(float2*)&sZ[g][sub][2 * hl] = make_float2(z0, z1);
        *(float2*)&sT[g][sub][2 * hl] = make_float2(t0, t1);
        __syncthreads();

        if (tid < 64) {
            const int sub2 = (tid >> 4) & 3, i2 = tid & 15;
            const int chain2 = (quad * 4 + sub2) * NHEAD + head;
            const long bz = (long)(chain2 * SPLIT + seg) * CHUNKS * 16 + i2;
            float rz = 0.f;
#pragma unroll
            for (int gg = 0; gg < CHUNKS; gg++) {
                g_prefZ[bz + gg * 16] = rz;
                rz += sZ[gg][sub2][i2];
            }
            g_totZ[(long)(chain2 * SPLIT + seg) * 16 + i2] = rz;
        } else {
            const int tt2 = tid - 64;
            const int sub2 = (tt2 >> 4) & 3, i2 = tt2 & 15;
            const int chain2 = (quad * 4 + sub2) * NHEAD + head;
            const long bt = (long)(chain2 * SPLIT + seg) * CHUNKS * 16 + i2;
            float rt = 0.f;
#pragma unroll
            for (int gg = 0; gg < CHUNKS; gg++) {
                g_prefT[bt + gg * 16] = rt;
                rt += sT[gg][sub2][i2];
            }
            g_totT[(long)(chain2 * SPLIT + seg) * 16 + i2] = rt;
        }
    }
}

// ---------------------------------------------------------------------------
// K2: exclusive prefix of segment totals across SPLIT segments of each chain
// (in place). grid = 160, block = 288.
// ---------------------------------------------------------------------------
__global__ void scan_b()
{
    const int chain = blockIdx.x;
    const int t = threadIdx.x;
    if (t < 256) {
        float run = 0.f;
#pragma unroll
        for (int s = 0; s < SPLIT; s++) {
            const long idx = ((long)chain * SPLIT + s) * 256 + t;
            const float v = g_totS[idx]; g_totS[idx] = run; run += v;
        }
    } else if (t < 272) {
        const int i = t - 256;
        float run = 0.f;
#pragma unroll
        for (int s = 0; s < SPLIT; s++) {
            const long idx = ((long)chain * SPLIT + s) * 16 + i;
            const float v = g_totZ[idx]; g_totZ[idx] = run; run += v;
        }
    } else {
        const int i = t - 272;
        float run = 0.f;
#pragma unroll
        for (int s = 0; s < SPLIT; s++) {
            const long idx = ((long)chain * SPLIT + s) * 16 + i;
            const float v = g_totT[idx]; g_totT[idx] = run; run += v;
        }
    }
}

// ---------------------------------------------------------------------------
// K3: batch-quad rescan from prefix state with q; 128-thread blocks (1 wave).
// Inner heads: full S rescan -> params scratch. Outer heads: light t/z
// rescan -> e-summed shifted output directly.
// ---------------------------------------------------------------------------
__global__ __launch_bounds__(128, 6) void scan_c(
    const float* __restrict__ x,
    const float* __restrict__ ew,
    const float* __restrict__ eb,
    const float* __restrict__ ind_out_b,
    const float* __restrict__ ind_res_w,
    float* __restrict__ out)
{
    __shared__ __align__(16) float st[2][CHUNKS][4][32];  // [buf][chunk][sub][k|q]

    const int b    = blockIdx.x;
    const int quad = b / (NHEAD * SPLIT);
    const int rem  = b % (NHEAD * SPLIT);
    const int seg  = rem / NHEAD;
    const int head = rem % NHEAD;
    const int tid  = threadIdx.x;
    const int g    = tid >> 5;
    const int sub  = (tid >> 3) & 3;
    const int hl   = tid & 7;

    const int n     = quad * 4 + sub;
    const int chain = n * NHEAD + head;
    const float* xw = x + (long)n * S_LEN;
    const int pos0  = seg * SEG_LEN + g * CLEN;

    const long qbase = (long)head * S_LEN * 8 + (long)pos0 * 8 + hl;
    const float2* wq = (const float2*)ew + qbase;
    const float2* bq = (const float2*)eb + qbase;

    if (head < 3) {
        // ---------------- inner heads ----------------
        float S0[16], S1[16], z0, z1;
        {
            const long pb = ((long)(chain * SPLIT + seg) * CHUNKS + g) * 256;
            const long tb = (long)(chain * SPLIT + seg) * 256;
#pragma unroll
            for (int i = 0; i < 16; i++) {
                const float2 p = *(const float2*)&g_prefS[pb + i * 16 + 2 * hl];
                const float2 t = *(const float2*)&g_totS[tb + i * 16 + 2 * hl];
                S0[i] = p.x + t.x; S1[i] = p.y + t.y;
            }
            const float2 pz = *(const float2*)&g_prefZ[
                ((long)(chain * SPLIT + seg) * CHUNKS + g) * 16 + 2 * hl];
            const float2 tz = *(const float2*)&g_totZ[
                (long)(chain * SPLIT + seg) * 16 + 2 * hl];
            z0 = pz.x + tz.x; z1 = pz.y + tz.y;
        }

        float* pdst = g_params + ((long)(n * 3 + head) * S_LEN) * EDIM;

        for (int s = 0; s < CLEN; s++) {
            const int pos = pos0 + s;
            const float xv = __ldg(xw + pos);
            float2 a, c;
            a = __ldg(wq + s * 8);         c = __ldg(bq + s * 8);
            const float qx = softplus_f(fmaf(a.x, xv, c.x));
            const float qy = softplus_f(fmaf(a.y, xv, c.y));
            a = __ldg(wq + KOFF2 + s * 8); c = __ldg(bq + KOFF2 + s * 8);
            const float kx = softplus_f(fmaf(a.x, xv, c.x));
            const float ky = softplus_f(fmaf(a.y, xv, c.y));
            a = __ldg(wq + VOFF2 + s * 8); c = __ldg(bq + VOFF2 + s * 8);
            const float vx = fmaf(a.x, xv, c.x);
            const float vy = fmaf(a.y, xv, c.y);

            z0 += kx; z1 += ky;

            const int buf = s & 1;
            *(float2*)&st[buf][g][sub][2 * hl]      = make_float2(kx, ky);
            *(float2*)&st[buf][g][sub][16 + 2 * hl] = make_float2(qx, qy);
            __syncwarp();

            float dp = fmaf(qx, z0, qy * z1);
            dp += __shfl_xor_sync(0xffffffffu, dp, 1, 8);
            dp += __shfl_xor_sync(0xffffffffu, dp, 2, 8);
            dp += __shfl_xor_sync(0xffffffffu, dp, 4, 8);

            const float4* kv = (const float4*)&st[buf][g][sub][0];
            const float4* qv = (const float4*)&st[buf][g][sub][16];
            float num0 = 0.f, num1 = 0.f;
#pragma unroll
            for (int q4 = 0; q4 < 4; q4++) {
                const float4 K = kv[q4];
                const float4 Q = qv[q4];
                S0[4*q4+0] = fmaf(K.x, vx, S0[4*q4+0]); num0 = fmaf(Q.x, S0[4*q4+0], num0);
                S0[4*q4+1] = fmaf(K.y, vx, S0[4*q4+1]); num0 = fmaf(Q.y, S0[4*q4+1], num0);
                S0[4*q4+2] = fmaf(K.z, vx, S0[4*q4+2]); num0 = fmaf(Q.z, S0[4*q4+2], num0);
                S0[4*q4+3] = fmaf(K.w, vx, S0[4*q4+3]); num0 = fmaf(Q.w, S0[4*q4+3], num0);
                S1[4*q4+0] = fmaf(K.x, vy, S1[4*q4+0]); num1 = fmaf(Q.x, S1[4*q4+0], num1);
                S1[4*q4+1] = fmaf(K.y, vy, S1[4*q4+1]); num1 = fmaf(Q.y, S1[4*q4+1], num1);
                S1[4*q4+2] = fmaf(K.z, vy, S1[4*q4+2]); num1 = fmaf(Q.z, S1[4*q4+2], num1);
                S1[4*q4+3] = fmaf(K.w, vy, S1[4*q4+3]); num1 = fmaf(Q.w, S1[4*q4+3], num1);
            }
            const float r = __fdividef(1.0f, dp);
            const float p0 = num0 * r, p1 = num1 * r;
            *(float2*)&pdst[(long)pos * EDIM + 2 * hl] = make_float2(p0, p1);
        }
    } else {
        // ---------------- outer heads: light path ----------------
        float z0, z1, t0, t1;
        {
            const long zb = ((long)(chain * SPLIT + seg) * CHUNKS + g) * 16 + 2 * hl;
            const long tb = (long)(chain * SPLIT + seg) * 16 + 2 * hl;
            const float2 pz = *(const float2*)&g_prefZ[zb];
            const float2 tz = *(const float2*)&g_totZ[tb];
            const float2 pt = *(const float2*)&g_prefT[zb];
            const float2 tt = *(const float2*)&g_totT[tb];
            z0 = pz.x + tz.x; z1 = pz.y + tz.y;
            t0 = pt.x + tt.x; t1 = pt.y + tt.y;
        }

        const long base = (long)3 * NBATCH * S_LEN * EDIM
                        + (long)(head - 3) * NBATCH * S_LEN;
        float* odst = out + base + (long)n * S_LEN;
        if (g == 0 && hl == 0 && seg == 0)
            odst[0] = (head == 3) ? ind_out_b[0] : ind_res_w[0];

        for (int s = 0; s < CLEN; s++) {
            const int pos = pos0 + s;
            const float xv = __ldg(xw + pos);
            float2 a, c;
            a = __ldg(wq + s * 8);         c = __ldg(bq + s * 8);
            const float qx = softplus_f(fmaf(a.x, xv, c.x));
            const float qy = softplus_f(fmaf(a.y, xv, c.y));
            a = __ldg(wq + KOFF2 + s * 8); c = __ldg(bq + KOFF2 + s * 8);
            const float kx = softplus_f(fmaf(a.x, xv, c.x));
            const float ky = softplus_f(fmaf(a.y, xv, c.y));
            a = __ldg(wq + VOFF2 + s * 8); c = __ldg(bq + VOFF2 + s * 8);
            const float vx = fmaf(a.x, xv, c.x);
            const float vy = fmaf(a.y, xv, c.y);

            float vs = vx + vy;
            vs += __shfl_xor_sync(0xffffffffu, vs, 1, 8);
            vs += __shfl_xor_sync(0xffffffffu, vs, 2, 8);
            vs += __shfl_xor_sync(0xffffffffu, vs, 4, 8);

            z0 += kx; z1 += ky;
            t0 = fmaf(kx, vs, t0);
            t1 = fmaf(ky, vs, t1);

            float dp = fmaf(qx, z0, qy * z1);
            float nm = fmaf(qx, t0, qy * t1);
            dp += __shfl_xor_sync(0xffffffffu, dp, 1, 8);
            nm += __shfl_xor_sync(0xffffffffu, nm, 1, 8);
            dp += __shfl_xor_sync(0xffffffffu, dp, 2, 8);
            nm += __shfl_xor_sync(0xffffffffu, nm, 2, 8);
            dp += __shfl_xor_sync(0xffffffffu, dp, 4, 8);
            nm += __shfl_xor_sync(0xffffffffu, nm, 4, 8);

            if (hl == 0 && pos + 1 < S_LEN)
                odst[pos + 1] = __fdividef(nm, dp);
        }
    }
}

// ---------------------------------------------------------------------------
// K4: per-position MLP for heads 0..2 on shifted params.
// 2 positions per thread (pos, pos+1536) sharing every weight load.
// (measured-best variant; unchanged)
// ---------------------------------------------------------------------------
__global__ __launch_bounds__(128) void mlp_kernel(
    const float* __restrict__ ind_in_w,
    const float* __restrict__ ind_in_b,
    const float* __restrict__ ind_out_w,
    const float* __restrict__ fc1_w,
    const float* __restrict__ fc1_b,
    const float* __restrict__ fc2_w,
    const float* __restrict__ fc2_b,
    float* __restrict__ out)
{
    __shared__ __align__(16) float w1[32 * 16];
    __shared__ __align__(16) float w2t[32][16];   // transposed: [o][e]
    __shared__ float b1[32];
    __shared__ float b2[16];

    const int tid = threadIdx.x;
    for (int i = tid; i < 512; i += 128) w1[i] = fc1_w[i];
    for (int i = tid; i < 512; i += 128) {
        const int p = i >> 5, o = i & 31;   // fc2_w is [E][2E] row-major
        w2t[o][p] = fc2_w[i];
    }
    if (tid < 32) b1[tid] = fc1_b[tid];
    if (tid < 16) b2[tid] = fc2_b[tid];
    __syncthreads();

    const int HALF = S_LEN / 2;                  // 1536
    const int t    = blockIdx.x * 128 + tid;     // 0 .. 147455
    const int n    = t / (3 * HALF);
    const int r    = t - n * (3 * HALF);
    const int tt   = r / HALF;
    const int posA = r - tt * HALF;
    const int posB = posA + HALF;

    const float* gp = g_params + (long)(n * 3 + tt) * S_LEN * EDIM;

    float pA[16], pB[16];
    if (posA == 0) {
#pragma unroll
        for (int e = 0; e < 16; e++) {
            pA[e] = (tt == 0) ? softplus_f(ind_in_w[e])
                  : (tt == 1) ? ind_in_b[e]
                              : ind_out_w[e];
        }
    } else {
        const float4* src = (const float4*)(gp + (long)(posA - 1) * EDIM);
        const float4 a = src[0], b = src[1], c = src[2], d = src[3];
        pA[0]=a.x; pA[1]=a.y; pA[2]=a.z; pA[3]=a.w;
        pA[4]=b.x; pA[5]=b.y; pA[6]=b.z; pA[7]=b.w;
        pA[8]=c.x; pA[9]=c.y; pA[10]=c.z; pA[11]=c.w;
        pA[12]=d.x; pA[13]=d.y; pA[14]=d.z; pA[15]=d.w;
    }
    {
        const float4* src = (const float4*)(gp + (long)(posB - 1) * EDIM);
        const float4 a = src[0], b = src[1], c = src[2], d = src[3];
        pB[0]=a.x; pB[1]=a.y; pB[2]=a.z; pB[3]=a.w;
        pB[4]=b.x; pB[5]=b.y; pB[6]=b.z; pB[7]=b.w;
        pB[8]=c.x; pB[9]=c.y; pB[10]=c.z; pB[11]=c.w;
        pB[12]=d.x; pB[13]=d.y; pB[14]=d.z; pB[15]=d.w;
    }

    float accA[16], accB[16];
#pragma unroll
    for (int e = 0; e < 16; e++) { accA[e] = b2[e]; accB[e] = b2[e]; }

#pragma unroll
    for (int o = 0; o < 32; o++) {
        const float4* w1p = (const float4*)&w1[o * 16];
        const float4 W0 = w1p[0], W1 = w1p[1], W2 = w1p[2], W3 = w1p[3];
        float hA0 = fmaf(pA[0], W0.x, 0.f),  hA1 = fmaf(pA[1], W0.y, 0.f);
        float hB0 = fmaf(pB[0], W0.x, 0.f),  hB1 = fmaf(pB[1], W0.y, 0.f);
        hA0 = fmaf(pA[2], W0.z, hA0); hA1 = fmaf(pA[3], W0.w, hA1);
        hB0 = fmaf(pB[2], W0.z, hB0); hB1 = fmaf(pB[3], W0.w, hB1);
        hA0 = fmaf(pA[4], W1.x, hA0); hA1 = fmaf(pA[5], W1.y, hA1);
        hB0 = fmaf(pB[4], W1.x, hB0); hB1 = fmaf(pB[5], W1.y, hB1);
        hA0 = fmaf(pA[6], W1.z, hA0); hA1 = fmaf(pA[7], W1.w, hA1);
        hB0 = fmaf(pB[6], W1.z, hB0); hB1 = fmaf(pB[7], W1.w, hB1);
        hA0 = fmaf(pA[8], W2.x, hA0); hA1 = fmaf(pA[9], W2.y, hA1);
        hB0 = fmaf(pB[8], W2.x, hB0); hB1 = fmaf(pB[9], W2.y, hB1);
        hA0 = fmaf(pA[10], W2.z, hA0); hA1 = fmaf(pA[11], W2.w, hA1);
        hB0 = fmaf(pB[10], W2.z, hB0); hB1 = fmaf(pB[11], W2.w, hB1);
        hA0 = fmaf(pA[12], W3.x, hA0); hA1 = fmaf(pA[13], W3.y, hA1);
        hB0 = fmaf(pB[12], W3.x, hB0); hB1 = fmaf(pB[13], W3.y, hB1);
        hA0 = fmaf(pA[14], W3.z, hA0); hA1 = fmaf(pA[15], W3.w, hA1);
        hB0 = fmaf(pB[14], W3.z, hB0); hB1 = fmaf(pB[15], W3.w, hB1);

        const float hA = fmaxf(hA0 + hA1 + b1[o], 0.0f);
        const float hB = fmaxf(hB0 + hB1 + b1[o], 0.0f);

        const float4* w2p = (const float4*)&w2t[o][0];
        const float4 V0 = w2p[0], V1 = w2p[1], V2 = w2p[2], V3 = w2p[3];
        accA[0] = fmaf(hA, V0.x, accA[0]);  accB[0] = fmaf(hB, V0.x, accB[0]);
        accA[1] = fmaf(hA, V0.y, accA[1]);  accB[1] = fmaf(hB, V0.y, accB[1]);
        accA[2] = fmaf(hA, V0.z, accA[2]);  accB[2] = fmaf(hB, V0.z, accB[2]);
        accA[3] = fmaf(hA, V0.w, accA[3]);  accB[3] = fmaf(hB, V0.w, accB[3]);
        accA[4] = fmaf(hA, V1.x, accA[4]);  accB[4] = fmaf(hB, V1.x, accB[4]);
        accA[5] = fmaf(hA, V1.y, accA[5]);  accB[5] = fmaf(hB, V1.y, accB[5]);
        accA[6] = fmaf(hA, V1.z, accA[6]);  accB[6] = fmaf(hB, V1.z, accB[6]);
        accA[7] = fmaf(hA, V1.w, accA[7]);  accB[7] = fmaf(hB, V1.w, accB[7]);
        accA[8] = fmaf(hA, V2.x, accA[8]);  accB[8] = fmaf(hB, V2.x, accB[8]);
        accA[9] = fmaf(hA, V2.y, accA[9]);  accB[9] = fmaf(hB, V2.y, accB[9]);
        accA[10] = fmaf(hA, V2.z, accA[10]); accB[10] = fmaf(hB, V2.z, accB[10]);
        accA[11] = fmaf(hA, V2.w, accA[11]); accB[11] = fmaf(hB, V2.w, accB[11]);
        accA[12] = fmaf(hA, V3.x, accA[12]); accB[12] = fmaf(hB, V3.x, accB[12]);
        accA[13] = fmaf(hA, V3.y, accA[13]); accB[13] = fmaf(hB, V3.y, accB[13]);
        accA[14] = fmaf(hA, V3.z, accA[14]); accB[14] = fmaf(hB, V3.z, accB[14]);
        accA[15] = fmaf(hA, V3.w, accA[15]); accB[15] = fmaf(hB, V3.w, accB[15]);
    }

    if (tt == 0) {   // in_proj_weight gets a final softplus
#pragma unroll
        for (int e = 0; e < 16; e++) {
            accA[e] = softplus_f(accA[e]);
            accB[e] = softplus_f(accB[e]);
        }
    }

    float* dbase = out + ((long)tt * NBATCH + n) * S_LEN * EDIM;
    float4* dA = (float4*)(dbase + (long)posA * EDIM);
    dA[0] = make_float4(accA[0],  accA[1],  accA[2],  accA[3]);
    dA[1] = make_float4(accA[4],  accA[5],  accA[6],  accA[7]);
    dA[2] = make_float4(accA[8],  accA[9],  accA[10], accA[11]);
    dA[3] = make_float4(accA[12], accA[13], accA[14], accA[15]);
    float4* dB = (float4*)(dbase + (long)posB * EDIM);
    dB[0] = make_float4(accB[0],  accB[1],  accB[2],  accB[3]);
    dB[1] = make_float4(accB[4],  accB[5],  accB[6],  accB[7]);
    dB[2] = make_float4(accB[8],  accB[9],  accB[10], accB[11]);
    dB[3] = make_float4(accB[12], accB[13], accB[14], accB[15]);
}

// ---------------------------------------------------------------------------
extern "C" void kernel_launch(void* const* d_in, const int* in_sizes, int n_in,
                              void* d_out, int out_size)
{
    const float* x         = (const float*)d_in[0];
    const float* ew        = (const float*)d_in[1];
    const float* eb        = (const float*)d_in[2];
    const float* ind_in_w  = (const float*)d_in[3];
    const float* ind_in_b  = (const float*)d_in[4];
    const float* ind_out_w = (const float*)d_in[5];
    const float* ind_out_b = (const float*)d_in[6];
    const float* ind_res_w = (const float*)d_in[7];
    const float* fc1_w     = (const float*)d_in[8];
    const float* fc1_b     = (const float*)d_in[9];
    const float* fc2_w     = (const float*)d_in[10];
    const float* fc2_b     = (const float*)d_in[11];
    float* out = (float*)d_out;

    scan_a<<<NQUAD * NHEAD * SPLIT, 128>>>(x, ew, eb);
    scan_b<<<NCHAIN, 288>>>();
    scan_c<<<NQUAD * NHEAD * SPLIT, 128>>>(x, ew, eb, ind_out_b, ind_res_w, out);
    mlp_kernel<<<(NBATCH * 3 * (S_LEN / 2)) / 128, 128>>>(
        ind_in_w, ind_in_b, ind_out_w, fc1_w, fc1_b, fc2_w, fc2_b, out);
}